// round 16
// baseline (speedup 1.0000x reference)
#include <cuda_runtime.h>

#define T_STEPS 8192
#define IDIM 256
#define HDIM 1024
#define NBLOCKS 128
#define NTHREADS 256       // 8 warps; warp w handles h index j = 8*block + w
#define NAN_BITS 0x7fc00000u
#define LOG2E 1.4426950408889634f

// h history: row t holds h_{t-1} (input to step t). Row 0 = zeros (h_0).
// Rows 1..T start as sentinel NaN. Each element is written EXACTLY ONCE,
// so any non-sentinel read is the final value — the validated load IS the
// synchronization. h = o*tanh(c) ∈ (-1,1) never equals the sentinel.
__device__ __align__(16) float g_hs[(T_STEPS + 1) * HDIM];

__global__ void init_kernel() {
    unsigned int v = (blockIdx.x == 0) ? 0u : NAN_BITS;
    uint4 q = make_uint4(v, v, v, v);
    reinterpret_cast<uint4*>(g_hs + (size_t)blockIdx.x * HDIM)[threadIdx.x] = q;
}

__device__ __forceinline__ float sigmoid_fast(float x) {
    return 1.0f / (1.0f + __expf(-x));
}
// Packed dual-FMA: d.xy += a.xy * b.xy  (Blackwell f32x2, PTX-only)
__device__ __forceinline__ void fma2(unsigned long long& d,
                                     unsigned long long a,
                                     unsigned long long b) {
    asm("fma.rn.f32x2 %0, %1, %2, %0;" : "+l"(d) : "l"(a), "l"(b));
}
__device__ __forceinline__ unsigned long long ld64(const float* p) {
    return *reinterpret_cast<const unsigned long long*>(p);
}
__device__ __forceinline__ unsigned long long pack2(unsigned int x, unsigned int y) {
    unsigned long long d;
    asm("mov.b64 %0, {%1,%2};" : "=l"(d) : "r"(x), "r"(y));
    return d;
}
__device__ __forceinline__ unsigned long long add2(unsigned long long a,
                                                   unsigned long long b) {
    unsigned long long d;
    asm("add.rn.f32x2 %0, %1, %2;" : "=l"(d) : "l"(a), "l"(b));
    return d;
}
__device__ __forceinline__ float pairsum(unsigned long long v) {
    float2 f = *reinterpret_cast<float2*>(&v);
    return f.x + f.y;
}
__device__ __forceinline__ float ex2_approx(float x) {
    float r; asm("ex2.approx.f32 %0, %1;" : "=f"(r) : "f"(x)); return r;
}
__device__ __forceinline__ float rcp_approx(float x) {
    float r; asm("rcp.approx.f32 %0, %1;" : "=f"(r) : "f"(x)); return r;
}

__global__ void __launch_bounds__(NTHREADS, 1)
lstm_kernel(const float* __restrict__ seq,
            const float* __restrict__ W_ih,
            const float* __restrict__ W_hh,
            const float* __restrict__ b_ih,
            const float* __restrict__ b_hh)
{
    __shared__ __align__(16) float h_s[HDIM];   // single buffer (R9 frame)

    const int tid  = threadIdx.x;
    const int warp = tid >> 5;
    const int lane = tid & 31;
    const int j    = blockIdx.x * 8 + warp;     // h index this warp owns
    const int gate = lane & 3;                  // this lane's gate
    const int iq   = lane >> 2;                 // quad slot 0..7

    // This lane's gate row; lane covers column quads 4*iq + 32*k.
    const int rowg = j + gate * HDIM;
    const int cbase = 4 * iq;

    // ---- Recurrent weights for ONE gate row, 128 columns per lane,
    // register-resident as f32x2 pairs (lo = cols q..q+1, hi = q+2..q+3). ----
    unsigned long long whl[32], whh[32];
    #pragma unroll
    for (int k = 0; k < 32; k++) {
        const float* b = W_hh + (size_t)rowg * HDIM + cbase + 32 * k;
        whl[k] = ld64(b);
        whh[k] = ld64(b + 2);
    }
    // ---- Input-projection weights, same map (k = 0..7). ----
    unsigned long long wxl[8], wxh[8];
    #pragma unroll
    for (int k = 0; k < 8; k++) {
        const float* b = W_ih + (size_t)rowg * IDIM + cbase + 32 * k;
        wxl[k] = ld64(b);
        wxh[k] = ld64(b + 2);
    }

    // Per-lane activation constants with log2(e) folded in:
    //   sigmoid(x) = rcp(1 + 2^(-log2e*x));  tanh(x) = 2*rcp(1+2^(-2log2e*x))-1
    const float bias_lane = b_ih[rowg] + b_hh[rowg];
    const float pre2  = (gate == 2) ? (-2.0f * LOG2E) : (-LOG2E);
    const float biasp = pre2 * bias_lane;
    const float postA = (gate == 2) ?  2.0f :  1.0f;
    const float postB = (gate == 2) ? -1.0f :  0.0f;

    // x_t quads, prefetched one step ahead (4 gate-lanes share addresses).
    uint4 xq[8];
    #pragma unroll
    for (int k = 0; k < 8; k++)
        xq[k] = *reinterpret_cast<const uint4*>(seq + cbase + 32 * k);

    float c_state = 0.0f;

    #pragma unroll 1
    for (int t = 0; t < T_STEPS; ++t) {
        // ---- x-projection FIRST (R9 order — law #4). ----
        unsigned long long accA = 0, accB = 0;
        #pragma unroll
        for (int k = 0; k < 8; k++) {
            fma2(accA, wxl[k], pack2(xq[k].x, xq[k].y));
            fma2(accB, wxh[k], pack2(xq[k].z, xq[k].w));
        }

        // ---- Sticky vote-poll (R9 structure: first load in-loop, ONE load
        // in flight, uniform __all_sync exit — laws #1, #2). ----
        const float* p = g_hs + (size_t)t * HDIM + 4 * tid;
        unsigned int v0, v1, v2, v3;
        int ok = 0;
        do {
            if (!ok) {
                asm volatile("ld.global.cg.v4.b32 {%0,%1,%2,%3}, [%4];"
                             : "=r"(v0), "=r"(v1), "=r"(v2), "=r"(v3) : "l"(p));
                ok = (v0 != NAN_BITS) & (v1 != NAN_BITS) &
                     (v2 != NAN_BITS) & (v3 != NAN_BITS);
            }
        } while (!__all_sync(0xffffffffu, ok));

        // Stage this warp's segment (layout identical to R9).
        reinterpret_cast<uint4*>(h_s)[tid] = make_uint4(v0, v1, v2, v3);
        __syncthreads();

        // ---- Recurrent matvec, per-gate partition: one LDS.128 per quad
        // (16B aligned; lanes 0..7 hit distinct banks, 4 gate-lanes
        // broadcast), 2 fma2 per quad, 64 fma2 total (vs 80 in R9). ----
        #pragma unroll
        for (int k = 0; k < 32; k++) {
            uint4 hv = *reinterpret_cast<const uint4*>(h_s + cbase + 32 * k);
            fma2(accA, whl[k], pack2(hv.x, hv.y));
            fma2(accB, whh[k], pack2(hv.z, hv.w));
        }

        // ---- Reduce: combine accumulators, then ONLY 3 butterfly stages
        // over the 8-lane gate group (xor 4, 8, 16). Lanes 0..3 end up
        // holding totals for gates 0..3. ----
        float s = pairsum(add2(accA, accB));
        s += __shfl_xor_sync(0xffffffffu, s, 4);
        s += __shfl_xor_sync(0xffffffffu, s, 8);
        s += __shfl_xor_sync(0xffffffffu, s, 16);

        // ---- ONE nonlinearity per lane (ex2 + rcp approx, log2e folded). ----
        float act = fmaf(postA,
                         rcp_approx(1.0f + ex2_approx(fmaf(pre2, s, biasp))),
                         postB);
        float i_ = __shfl_sync(0xffffffffu, act, 0);
        float f_ = __shfl_sync(0xffffffffu, act, 1);
        float g_ = __shfl_sync(0xffffffffu, act, 2);
        float o_ = __shfl_sync(0xffffffffu, act, 3);

        c_state = f_ * c_state + i_ * g_;
        float tc = fmaf(2.0f,
                        rcp_approx(1.0f + ex2_approx(-2.0f * LOG2E * c_state)),
                        -1.0f);
        float h_ = o_ * tc;
        // Publish ASAP (law #3): lane 0, immediately after the cell.
        if (lane == 0) {
            asm volatile("st.global.cg.f32 [%0], %1;"
                         :: "l"(g_hs + (size_t)(t + 1) * HDIM + j), "f"(h_));
        }

        // ---- Prefetch x_{t+1}; hides behind the next poll. ----
        if (t + 1 < T_STEPS) {
            const float* xrow = seq + (size_t)(t + 1) * IDIM + cbase;
            #pragma unroll
            for (int k = 0; k < 8; k++)
                xq[k] = *reinterpret_cast<const uint4*>(xrow + 32 * k);
        }

        __syncthreads();    // trailing barrier (R9 frame): parks warps at BAR,
                            // keeping chip-wide poll traffic under the LTS cap.
    }
}

// out[t] = sigmoid(h_{t+1} . W_out + b_out); one warp per timestep.
__global__ void __launch_bounds__(256)
out_kernel(const float* __restrict__ W_out,
           const float* __restrict__ b_out,
           float* __restrict__ out)
{
    const int warp = threadIdx.x >> 5;
    const int lane = threadIdx.x & 31;
    const int t = blockIdx.x * 8 + warp;
    if (t >= T_STEPS) return;

    const float* hrow = g_hs + (size_t)(t + 1) * HDIM;
    float acc = 0.0f;
    #pragma unroll
    for (int k = 0; k < 32; k++) {
        int c = lane + 32 * k;
        acc = fmaf(hrow[c], W_out[c], acc);
    }
    #pragma unroll
    for (int off = 16; off > 0; off >>= 1)
        acc += __shfl_xor_sync(0xffffffffu, acc, off);
    if (lane == 0)
        out[t] = sigmoid_fast(acc + b_out[0]);
}

extern "C" void kernel_launch(void* const* d_in, const int* in_sizes, int n_in,
                              void* d_out, int out_size)
{
    const float* seq   = (const float*)d_in[0];   // [8192, 256]
    const float* W_ih  = (const float*)d_in[1];   // [4096, 256]
    const float* W_hh  = (const float*)d_in[2];   // [4096, 1024]
    const float* b_ih  = (const float*)d_in[3];   // [4096]
    const float* b_hh  = (const float*)d_in[4];   // [4096]
    const float* W_out = (const float*)d_in[5];   // [1, 1024]
    const float* b_out = (const float*)d_in[6];   // [1]
    float* out = (float*)d_out;                   // [8192, 1]

    init_kernel<<<T_STEPS + 1, NTHREADS>>>();
    lstm_kernel<<<NBLOCKS, NTHREADS>>>(seq, W_ih, W_hh, b_ih, b_hh);
    out_kernel<<<T_STEPS / 8, 256>>>(W_out, b_out, out);
}